// round 14
// baseline (speedup 1.0000x reference)
#include <cuda_runtime.h>
#include <cuda_fp16.h>
#include <math.h>
#include <float.h>
#include <stdint.h>

// Problem constants
#define BATCH   32
#define TLEN    2048
#define MROWS   (BATCH * TLEN)   // 65536
#define DIN     1024             // EPROJS = DUNITS
#define NATT    512              // ATT_DIM
#define NCH     32               // ACONV_CHANS
#define KFILT   31               // 2*15+1
#define TCHUNKS 16               // T/128 for weighted-sum partials

#define KTOT    1056             // 1024 (enc) + 32 (conv channels)
#define NCHUNKS 33               // KTOT / 32
#define NSLICES 4                // 512 / 128 N-tiles

// ---------------- scratch (__device__ globals) ---------------------------------------
__device__ float g_bias[BATCH * NATT];                 // dec_z@W_dec + b_enc
__device__ float g_attc[(size_t)MROWS * NCH];          // conv output (M,32) fp32
__device__ float g_epart[NSLICES * MROWS];             // energy partials per N-slice
__device__ float g_cpart[TCHUNKS * BATCH * DIN];       // context partials
// fp16 weights, B^T layout [n][k] (k-contiguous)
__device__ __half g_Bp[(size_t)NATT * KTOT];

// ---------------- PTX helpers --------------------------------------------------------
__device__ __forceinline__ uint32_t smem_u32(const void* p) {
    uint32_t a;
    asm("{ .reg .u64 t; cvta.to.shared.u64 t, %1; cvt.u32.u64 %0, t; }" : "=r"(a) : "l"(p));
    return a;
}
__device__ __forceinline__ void ldmx4(uint32_t* r, uint32_t addr) {
    asm volatile("ldmatrix.sync.aligned.m8n8.x4.shared.b16 {%0,%1,%2,%3}, [%4];"
                 : "=r"(r[0]), "=r"(r[1]), "=r"(r[2]), "=r"(r[3]) : "r"(addr));
}
__device__ __forceinline__ void mma16816(float* d, const uint32_t* a, const uint32_t* b) {
    asm volatile(
        "mma.sync.aligned.m16n8k16.row.col.f32.f16.f16.f32 "
        "{%0,%1,%2,%3}, {%4,%5,%6,%7}, {%8,%9}, {%0,%1,%2,%3};"
        : "+f"(d[0]), "+f"(d[1]), "+f"(d[2]), "+f"(d[3])
        : "r"(a[0]), "r"(a[1]), "r"(a[2]), "r"(a[3]), "r"(b[0]), "r"(b[1]));
}

// ---------------- kernel A: bias[b][a] = b_enc[a] + dec_z[b,:]@W_dec[:,a] ------------
__global__ void bias_kernel(const float* __restrict__ dec_z,
                            const float* __restrict__ W_dec,
                            const float* __restrict__ b_enc) {
    int b = blockIdx.x;
    int a = threadIdx.x;
    const float* dz = dec_z + b * DIN;
    float acc = b_enc[a];
    #pragma unroll 4
    for (int d = 0; d < DIN; d++)
        acc += dz[d] * W_dec[d * NATT + a];
    g_bias[b * NATT + a] = acc;
}

// ---------------- kernel B: location conv -> g_attc (M,32) fp32 ----------------------
__global__ void conv_kernel(const float* __restrict__ att_prev,
                            const float* __restrict__ conv_w) {
    __shared__ float cw[NCH * KFILT];
    for (int i = threadIdx.x; i < NCH * KFILT; i += blockDim.x)
        cw[i] = conv_w[i];
    __syncthreads();

    int idx = blockIdx.x * blockDim.x + threadIdx.x;   // b*T + t
    int b = idx >> 11;
    int t = idx & (TLEN - 1);
    const float* ap = att_prev + b * TLEN;

    float win[KFILT];
    #pragma unroll
    for (int k = 0; k < KFILT; k++) {
        int tt = t + k - (KFILT / 2);
        win[k] = (tt >= 0 && tt < TLEN) ? ap[tt] : 0.0f;
    }
    float* out = g_attc + (size_t)idx * NCH;
    #pragma unroll
    for (int c = 0; c < NCH; c++) {
        float s = 0.0f;
        #pragma unroll
        for (int k = 0; k < KFILT; k++)
            s += cw[c * KFILT + k] * win[k];
        out[c] = s;
    }
}

// ---------------- kernel C: weight prep -> fp16, B^T [n][k] layout -------------------
__global__ void wprep_kernel(const float* __restrict__ W_enc,
                             const float* __restrict__ W_att) {
    int n = blockIdx.x;                    // 0..511
    for (int k = threadIdx.x; k < KTOT; k += 256) {
        float w = (k < DIN) ? W_enc[(size_t)k * NATT + n]
                            : W_att[(size_t)(k - DIN) * NATT + n];
        g_Bp[(size_t)n * KTOT + k] = __float2half_rn(w);
    }
}

// ---------------- kernel D: mma.sync fused energy GEMM (single-pass fp16) ------------
// CTA tile 128m x 128n, K = 1056 in 33 chunks of 32, fp32 accumulators.
// Epilogue: +bias, tanh, dot W_g -> g_epart. Energies never hit DRAM.
#define LDS_ROW 40                 // fp16 elements per smem row (80B, conflict-free)
#define STAGE_BYTES 20480
#define OFF_AH 0
#define OFF_BH 10240
#define OFF_BIAS 40960
#define OFF_WG   41472
#define OFF_RED  41984             // red[128][8] fp32
#define SMEM_TOTAL 46080

__global__ void __launch_bounds__(256, 2)
energy_mma(const float* __restrict__ enc, const float* __restrict__ W_g) {
    extern __shared__ char smem[];
    const uint32_t sb = smem_u32(smem);
    const int tid  = threadIdx.x;
    const int wid  = tid >> 5;
    const int lane = tid & 31;
    const int warp_m = wid & 3;            // 4 warps over m (32-row bands)
    const int warp_n = wid >> 2;           // 2 warps over n (64-col bands)

    const int slice = blockIdx.x;          // n-tile 0..3 (fastest -> A reuse in L2)
    const int n0    = slice * 128;
    const int row0  = blockIdx.y * 128;
    const int b     = row0 >> 11;

    // per-thread invariant ldmatrix offsets (bytes)
    const uint32_t aoff0 = ((warp_m * 32 + (lane & 15)) * LDS_ROW + (lane >> 4) * 8) * 2;
    const uint32_t boff0 = ((warp_n * 64 + ((lane >> 4) & 1) * 8 + (lane & 7)) * LDS_ROW
                            + ((lane >> 3) & 1) * 8) * 2;

    float acc[2][8][4];
    #pragma unroll
    for (int i = 0; i < 2; i++)
        #pragma unroll
        for (int j = 0; j < 8; j++)
            #pragma unroll
            for (int q = 0; q < 4; q++) acc[i][j][q] = 0.0f;

    // ---- staging registers (fp16-packed at load time) ----
    uint2 a_st[4];
    uint4 b_st[2];

    auto load_regs = [&](int c) {
        const float* asrc;
        int lda;
        if (c < 32) { asrc = enc + (size_t)row0 * DIN + c * 32; lda = DIN; }
        else        { asrc = g_attc + (size_t)row0 * NCH;       lda = NCH; }
        #pragma unroll
        for (int i = 0; i < 4; i++) {
            int idx = tid + 256 * i;
            int r   = idx >> 3;
            int kg  = idx & 7;
            float4 f = *(const float4*)(asrc + (size_t)r * lda + kg * 4);
            __half2 h01 = __floats2half2_rn(f.x, f.y);
            __half2 h23 = __floats2half2_rn(f.z, f.w);
            a_st[i] = make_uint2(*(uint32_t*)&h01, *(uint32_t*)&h23);
        }
        int k0 = c * 32;
        #pragma unroll
        for (int i = 0; i < 2; i++) {
            int idx = tid + 256 * i;
            int n   = idx >> 2;
            int q   = idx & 3;
            b_st[i] = *(const uint4*)(g_Bp + (size_t)(n0 + n) * KTOT + k0 + q * 8);
        }
    };
    auto store_stage = [&](int s) {
        char* st = smem + s * STAGE_BYTES;
        #pragma unroll
        for (int i = 0; i < 4; i++) {
            int idx = tid + 256 * i;
            int r   = idx >> 3;
            int kg  = idx & 7;
            *(uint2*)(st + OFF_AH + (uint32_t)(r * LDS_ROW + kg * 4) * 2) = a_st[i];
        }
        #pragma unroll
        for (int i = 0; i < 2; i++) {
            int idx = tid + 256 * i;
            int n   = idx >> 2;
            int q   = idx & 3;
            *(uint4*)(st + OFF_BH + (uint32_t)(n * LDS_ROW + q * 8) * 2) = b_st[i];
        }
    };

    // ---- pipeline: stage0 prologue ----
    load_regs(0);
    store_stage(0);
    __syncthreads();

    for (int c = 0; c < NCHUNKS; c++) {
        const int s = c & 1;
        if (c + 1 < NCHUNKS) load_regs(c + 1);

        const uint32_t sbase = sb + s * STAGE_BYTES;
        #pragma unroll
        for (int ks = 0; ks < 2; ks++) {
            uint32_t ah[2][4];
            #pragma unroll
            for (int mi = 0; mi < 2; mi++) {
                uint32_t ao = aoff0 + mi * (16 * LDS_ROW * 2) + ks * 32;
                ldmx4(ah[mi], sbase + OFF_AH + ao);
            }
            #pragma unroll
            for (int njp = 0; njp < 4; njp++) {
                uint32_t bh[4];
                uint32_t bo = boff0 + njp * (16 * LDS_ROW * 2) + ks * 32;
                ldmx4(bh, sbase + OFF_BH + bo);
                #pragma unroll
                for (int mi = 0; mi < 2; mi++) {
                    mma16816(acc[mi][2 * njp],     ah[mi], bh);
                    mma16816(acc[mi][2 * njp + 1], ah[mi], bh + 2);
                }
            }
        }

        if (c + 1 < NCHUNKS) store_stage(s ^ 1);
        __syncthreads();
    }

    // ---- epilogue: +bias, tanh, dot W_g, reduce N-slice ----
    float* bias_s = (float*)(smem + OFF_BIAS);
    float* wg_s   = (float*)(smem + OFF_WG);
    float* red    = (float*)(smem + OFF_RED);
    if (tid < 128) {
        bias_s[tid] = g_bias[b * NATT + n0 + tid];
        wg_s[tid]   = W_g[n0 + tid];
    }
    __syncthreads();

    const int g  = lane >> 2;       // row group 0..7
    const int c4 = lane & 3;        // col group 0..3
    #pragma unroll
    for (int mi = 0; mi < 2; mi++) {
        #pragma unroll
        for (int rr = 0; rr < 2; rr++) {
            float s = 0.0f;
            #pragma unroll
            for (int j = 0; j < 8; j++) {
                int nl0 = warp_n * 64 + j * 8 + c4 * 2;
                s += tanhf(acc[mi][j][rr * 2 + 0] + bias_s[nl0])     * wg_s[nl0];
                s += tanhf(acc[mi][j][rr * 2 + 1] + bias_s[nl0 + 1]) * wg_s[nl0 + 1];
            }
            int m = warp_m * 32 + mi * 16 + rr * 8 + g;
            red[m * 8 + warp_n * 4 + c4] = s;
        }
    }
    __syncthreads();
    if (tid < 128) {
        float s = 0.0f;
        #pragma unroll
        for (int x = 0; x < 8; x++) s += red[tid * 8 + x];
        g_epart[slice * MROWS + row0 + tid] = s;
    }
}

// ---------------- kernel E: masked softmax over T per batch row ----------------------
__global__ void softmax_kernel(const int* __restrict__ lens,
                               const float* __restrict__ b_g,
                               float* __restrict__ out_w) {
    int b = blockIdx.x;
    __shared__ float es[TLEN];
    __shared__ float rbuf[256];
    const int len = lens[b];
    const float bg = b_g[0];

    float lmax = -FLT_MAX;
    for (int t = threadIdx.x; t < TLEN; t += 256) {
        int idx = b * TLEN + t;
        float e = bg + g_epart[idx] + g_epart[MROWS + idx]
                     + g_epart[2 * MROWS + idx] + g_epart[3 * MROWS + idx];
        e = (t < len) ? 2.0f * e : -INFINITY;   // SCALING=2, mask t>=len
        es[t] = e;
        lmax = fmaxf(lmax, e);
    }
    rbuf[threadIdx.x] = lmax;
    __syncthreads();
    for (int s = 128; s > 0; s >>= 1) {
        if (threadIdx.x < s)
            rbuf[threadIdx.x] = fmaxf(rbuf[threadIdx.x], rbuf[threadIdx.x + s]);
        __syncthreads();
    }
    float mx = rbuf[0];
    __syncthreads();

    float lsum = 0.0f;
    for (int t = threadIdx.x; t < TLEN; t += 256) {
        float v = expf(es[t] - mx);
        es[t] = v;
        lsum += v;
    }
    rbuf[threadIdx.x] = lsum;
    __syncthreads();
    for (int s = 128; s > 0; s >>= 1) {
        if (threadIdx.x < s)
            rbuf[threadIdx.x] += rbuf[threadIdx.x + s];
        __syncthreads();
    }
    float inv = 1.0f / rbuf[0];
    for (int t = threadIdx.x; t < TLEN; t += 256)
        out_w[b * TLEN + t] = es[t] * inv;
}

// ---------------- kernel F: partial weighted sums ------------------------------------
__global__ void wsum_kernel(const float* __restrict__ enc,
                            const float* __restrict__ w) {
    int b  = blockIdx.x;
    int tc = blockIdx.y;
    __shared__ float ws[128];
    int t0 = tc * 128;
    if (threadIdx.x < 128)
        ws[threadIdx.x] = w[b * TLEN + t0 + threadIdx.x];
    __syncthreads();

    int d = threadIdx.x;
    float a0 = 0, a1 = 0, a2 = 0, a3 = 0;
    const float* base = enc + ((size_t)b * TLEN + t0) * DIN;
    #pragma unroll 4
    for (int tt = 0; tt < 128; tt++) {
        const float* r = base + (size_t)tt * DIN;
        float wv = ws[tt];
        a0 += r[d]       * wv;
        a1 += r[d + 256] * wv;
        a2 += r[d + 512] * wv;
        a3 += r[d + 768] * wv;
    }
    float* cp = g_cpart + ((size_t)tc * BATCH + b) * DIN;
    cp[d]       = a0;
    cp[d + 256] = a1;
    cp[d + 512] = a2;
    cp[d + 768] = a3;
}

// ---------------- kernel G: reduce context partials ----------------------------------
__global__ void creduce_kernel(float* __restrict__ out_c) {
    int i = blockIdx.x * blockDim.x + threadIdx.x;
    if (i >= BATCH * DIN) return;
    float s = 0.0f;
    #pragma unroll
    for (int tc = 0; tc < TCHUNKS; tc++)
        s += g_cpart[(size_t)tc * BATCH * DIN + i];
    out_c[i] = s;
}

// ---------------- launch -------------------------------------------------------------
extern "C" void kernel_launch(void* const* d_in, const int* in_sizes, int n_in,
                              void* d_out, int out_size) {
    const float* enc      = (const float*)d_in[0];   // (32,2048,1024)
    const int*   lens     = (const int*)  d_in[1];   // (32,)
    const float* dec_z    = (const float*)d_in[2];   // (32,1024)
    const float* att_prev = (const float*)d_in[3];   // (32,2048)
    const float* W_enc    = (const float*)d_in[4];   // (1024,512)
    const float* b_enc    = (const float*)d_in[5];   // (512,)
    const float* W_dec    = (const float*)d_in[6];   // (1024,512)
    const float* W_att    = (const float*)d_in[7];   // (32,512)
    const float* conv_w   = (const float*)d_in[8];   // (32,1,31)
    const float* W_g      = (const float*)d_in[9];   // (512,1)
    const float* b_g      = (const float*)d_in[10];  // (1,)

    float* out   = (float*)d_out;
    float* out_c = out;                  // (32,1024)
    float* out_w = out + BATCH * DIN;    // (32,2048)

    cudaFuncSetAttribute(energy_mma, cudaFuncAttributeMaxDynamicSharedMemorySize, SMEM_TOTAL);

    bias_kernel<<<BATCH, NATT>>>(dec_z, W_dec, b_enc);
    conv_kernel<<<MROWS / 256, 256>>>(att_prev, conv_w);
    wprep_kernel<<<NATT, 256>>>(W_enc, W_att);
    energy_mma<<<dim3(NSLICES, MROWS / 128), 256, SMEM_TOTAL>>>(enc, W_g);
    softmax_kernel<<<BATCH, 256>>>(lens, b_g, out_w);
    wsum_kernel<<<dim3(BATCH, TCHUNKS), 256>>>(enc, out_w);
    creduce_kernel<<<(BATCH * DIN + 255) / 256, 256>>>(out_c);
}

// round 15
// speedup vs baseline: 1.0015x; 1.0015x over previous
#include <cuda_runtime.h>
#include <cuda_fp16.h>
#include <math.h>
#include <float.h>
#include <stdint.h>

// Problem constants
#define BATCH   32
#define TLEN    2048
#define MROWS   (BATCH * TLEN)   // 65536
#define DIN     1024             // EPROJS = DUNITS
#define NATT    512              // ATT_DIM
#define NCH     32               // ACONV_CHANS
#define KFILT   31               // 2*15+1
#define TCHUNKS 16               // T/128 for weighted-sum partials

#define KTOT    1056             // 1024 (enc) + 32 (conv channels)
#define NCHUNKS 33               // KTOT / 32
#define NSLICES 4                // 512 / 128 N-tiles

// ---------------- scratch (__device__ globals) ---------------------------------------
__device__ float g_bias[BATCH * NATT];                 // dec_z@W_dec + b_enc
__device__ float g_attc[(size_t)MROWS * NCH];          // conv output (M,32) fp32
__device__ float g_epart[NSLICES * MROWS];             // energy partials per N-slice
__device__ float g_cpart[TCHUNKS * BATCH * DIN];       // context partials
// fp16 weights, B^T layout [n][k] (k-contiguous)
__device__ __half g_Bp[(size_t)NATT * KTOT];

// ---------------- PTX helpers --------------------------------------------------------
__device__ __forceinline__ uint32_t smem_u32(const void* p) {
    uint32_t a;
    asm("{ .reg .u64 t; cvta.to.shared.u64 t, %1; cvt.u32.u64 %0, t; }" : "=r"(a) : "l"(p));
    return a;
}
__device__ __forceinline__ void ldmx4(uint32_t* r, uint32_t addr) {
    asm volatile("ldmatrix.sync.aligned.m8n8.x4.shared.b16 {%0,%1,%2,%3}, [%4];"
                 : "=r"(r[0]), "=r"(r[1]), "=r"(r[2]), "=r"(r[3]) : "r"(addr));
}
__device__ __forceinline__ void mma16816(float* d, const uint32_t* a, const uint32_t* b) {
    asm volatile(
        "mma.sync.aligned.m16n8k16.row.col.f32.f16.f16.f32 "
        "{%0,%1,%2,%3}, {%4,%5,%6,%7}, {%8,%9}, {%0,%1,%2,%3};"
        : "+f"(d[0]), "+f"(d[1]), "+f"(d[2]), "+f"(d[3])
        : "r"(a[0]), "r"(a[1]), "r"(a[2]), "r"(a[3]), "r"(b[0]), "r"(b[1]));
}

// ---------------- kernel A: bias[b][a] = b_enc[a] + dec_z[b,:]@W_dec[:,a] ------------
__global__ void bias_kernel(const float* __restrict__ dec_z,
                            const float* __restrict__ W_dec,
                            const float* __restrict__ b_enc) {
    int b = blockIdx.x;
    int a = threadIdx.x;
    const float* dz = dec_z + b * DIN;
    float acc = b_enc[a];
    #pragma unroll 4
    for (int d = 0; d < DIN; d++)
        acc += dz[d] * W_dec[d * NATT + a];
    g_bias[b * NATT + a] = acc;
}

// ---------------- kernel B: location conv -> g_attc (M,32) fp32 ----------------------
__global__ void conv_kernel(const float* __restrict__ att_prev,
                            const float* __restrict__ conv_w) {
    __shared__ float cw[NCH * KFILT];
    for (int i = threadIdx.x; i < NCH * KFILT; i += blockDim.x)
        cw[i] = conv_w[i];
    __syncthreads();

    int idx = blockIdx.x * blockDim.x + threadIdx.x;   // b*T + t
    int b = idx >> 11;
    int t = idx & (TLEN - 1);
    const float* ap = att_prev + b * TLEN;

    float win[KFILT];
    #pragma unroll
    for (int k = 0; k < KFILT; k++) {
        int tt = t + k - (KFILT / 2);
        win[k] = (tt >= 0 && tt < TLEN) ? ap[tt] : 0.0f;
    }
    float* out = g_attc + (size_t)idx * NCH;
    #pragma unroll
    for (int c = 0; c < NCH; c++) {
        float s = 0.0f;
        #pragma unroll
        for (int k = 0; k < KFILT; k++)
            s += cw[c * KFILT + k] * win[k];
        out[c] = s;
    }
}

// ---------------- kernel C: weight prep -> fp16, B^T [n][k] layout -------------------
__global__ void wprep_kernel(const float* __restrict__ W_enc,
                             const float* __restrict__ W_att) {
    int n = blockIdx.x;                    // 0..511
    for (int k = threadIdx.x; k < KTOT; k += 256) {
        float w = (k < DIN) ? W_enc[(size_t)k * NATT + n]
                            : W_att[(size_t)(k - DIN) * NATT + n];
        g_Bp[(size_t)n * KTOT + k] = __float2half_rn(w);
    }
}

// ---------------- kernel D: mma.sync fused energy GEMM (single-pass fp16) ------------
// CTA tile 128m x 128n, K = 1056 in 33 chunks of 32, fp32 accumulators.
// Epilogue: +bias, tanh, dot W_g -> g_epart. Energies never hit DRAM.
#define LDS_ROW 40                 // fp16 elements per smem row (80B, conflict-free)
#define STAGE_BYTES 20480
#define OFF_AH 0
#define OFF_BH 10240
#define OFF_BIAS 40960
#define OFF_WG   41472
#define OFF_RED  41984             // red[128][8] fp32
#define SMEM_TOTAL 46080

__global__ void __launch_bounds__(256, 2)
energy_mma(const float* __restrict__ enc, const float* __restrict__ W_g) {
    extern __shared__ char smem[];
    const uint32_t sb = smem_u32(smem);
    const int tid  = threadIdx.x;
    const int wid  = tid >> 5;
    const int lane = tid & 31;
    const int warp_m = wid & 3;            // 4 warps over m (32-row bands)
    const int warp_n = wid >> 2;           // 2 warps over n (64-col bands)

    const int slice = blockIdx.x;          // n-tile 0..3 (fastest -> A reuse in L2)
    const int n0    = slice * 128;
    const int row0  = blockIdx.y * 128;
    const int b     = row0 >> 11;

    // per-thread invariant ldmatrix offsets (bytes)
    const uint32_t aoff0 = ((warp_m * 32 + (lane & 15)) * LDS_ROW + (lane >> 4) * 8) * 2;
    const uint32_t boff0 = ((warp_n * 64 + ((lane >> 4) & 1) * 8 + (lane & 7)) * LDS_ROW
                            + ((lane >> 3) & 1) * 8) * 2;

    float acc[2][8][4];
    #pragma unroll
    for (int i = 0; i < 2; i++)
        #pragma unroll
        for (int j = 0; j < 8; j++)
            #pragma unroll
            for (int q = 0; q < 4; q++) acc[i][j][q] = 0.0f;

    // ---- staging registers (fp16-packed at load time) ----
    uint2 a_st[4];
    uint4 b_st[2];

    auto load_regs = [&](int c) {
        const float* asrc;
        int lda;
        if (c < 32) { asrc = enc + (size_t)row0 * DIN + c * 32; lda = DIN; }
        else        { asrc = g_attc + (size_t)row0 * NCH;       lda = NCH; }
        #pragma unroll
        for (int i = 0; i < 4; i++) {
            int idx = tid + 256 * i;
            int r   = idx >> 3;
            int kg  = idx & 7;
            float4 f = *(const float4*)(asrc + (size_t)r * lda + kg * 4);
            __half2 h01 = __floats2half2_rn(f.x, f.y);
            __half2 h23 = __floats2half2_rn(f.z, f.w);
            a_st[i] = make_uint2(*(uint32_t*)&h01, *(uint32_t*)&h23);
        }
        int k0 = c * 32;
        #pragma unroll
        for (int i = 0; i < 2; i++) {
            int idx = tid + 256 * i;
            int n   = idx >> 2;
            int q   = idx & 3;
            b_st[i] = *(const uint4*)(g_Bp + (size_t)(n0 + n) * KTOT + k0 + q * 8);
        }
    };
    auto store_stage = [&](int s) {
        char* st = smem + s * STAGE_BYTES;
        #pragma unroll
        for (int i = 0; i < 4; i++) {
            int idx = tid + 256 * i;
            int r   = idx >> 3;
            int kg  = idx & 7;
            *(uint2*)(st + OFF_AH + (uint32_t)(r * LDS_ROW + kg * 4) * 2) = a_st[i];
        }
        #pragma unroll
        for (int i = 0; i < 2; i++) {
            int idx = tid + 256 * i;
            int n   = idx >> 2;
            int q   = idx & 3;
            *(uint4*)(st + OFF_BH + (uint32_t)(n * LDS_ROW + q * 8) * 2) = b_st[i];
        }
    };

    // ---- pipeline: stage0 prologue ----
    load_regs(0);
    store_stage(0);
    __syncthreads();

    for (int c = 0; c < NCHUNKS; c++) {
        const int s = c & 1;
        if (c + 1 < NCHUNKS) load_regs(c + 1);

        const uint32_t sbase = sb + s * STAGE_BYTES;
        #pragma unroll
        for (int ks = 0; ks < 2; ks++) {
            uint32_t ah[2][4];
            #pragma unroll
            for (int mi = 0; mi < 2; mi++) {
                uint32_t ao = aoff0 + mi * (16 * LDS_ROW * 2) + ks * 32;
                ldmx4(ah[mi], sbase + OFF_AH + ao);
            }
            #pragma unroll
            for (int njp = 0; njp < 4; njp++) {
                uint32_t bh[4];
                uint32_t bo = boff0 + njp * (16 * LDS_ROW * 2) + ks * 32;
                ldmx4(bh, sbase + OFF_BH + bo);
                #pragma unroll
                for (int mi = 0; mi < 2; mi++) {
                    mma16816(acc[mi][2 * njp],     ah[mi], bh);
                    mma16816(acc[mi][2 * njp + 1], ah[mi], bh + 2);
                }
            }
        }

        if (c + 1 < NCHUNKS) store_stage(s ^ 1);
        __syncthreads();
    }

    // ---- epilogue: +bias, tanh, dot W_g, reduce N-slice ----
    float* bias_s = (float*)(smem + OFF_BIAS);
    float* wg_s   = (float*)(smem + OFF_WG);
    float* red    = (float*)(smem + OFF_RED);
    if (tid < 128) {
        bias_s[tid] = g_bias[b * NATT + n0 + tid];
        wg_s[tid]   = W_g[n0 + tid];
    }
    __syncthreads();

    const int g  = lane >> 2;       // row group 0..7
    const int c4 = lane & 3;        // col group 0..3
    #pragma unroll
    for (int mi = 0; mi < 2; mi++) {
        #pragma unroll
        for (int rr = 0; rr < 2; rr++) {
            float s = 0.0f;
            #pragma unroll
            for (int j = 0; j < 8; j++) {
                int nl0 = warp_n * 64 + j * 8 + c4 * 2;
                s += tanhf(acc[mi][j][rr * 2 + 0] + bias_s[nl0])     * wg_s[nl0];
                s += tanhf(acc[mi][j][rr * 2 + 1] + bias_s[nl0 + 1]) * wg_s[nl0 + 1];
            }
            int m = warp_m * 32 + mi * 16 + rr * 8 + g;
            red[m * 8 + warp_n * 4 + c4] = s;
        }
    }
    __syncthreads();
    if (tid < 128) {
        float s = 0.0f;
        #pragma unroll
        for (int x = 0; x < 8; x++) s += red[tid * 8 + x];
        g_epart[slice * MROWS + row0 + tid] = s;
    }
}

// ---------------- kernel E: masked softmax over T per batch row ----------------------
__global__ void softmax_kernel(const int* __restrict__ lens,
                               const float* __restrict__ b_g,
                               float* __restrict__ out_w) {
    int b = blockIdx.x;
    __shared__ float es[TLEN];
    __shared__ float rbuf[256];
    const int len = lens[b];
    const float bg = b_g[0];

    float lmax = -FLT_MAX;
    for (int t = threadIdx.x; t < TLEN; t += 256) {
        int idx = b * TLEN + t;
        float e = bg + g_epart[idx] + g_epart[MROWS + idx]
                     + g_epart[2 * MROWS + idx] + g_epart[3 * MROWS + idx];
        e = (t < len) ? 2.0f * e : -INFINITY;   // SCALING=2, mask t>=len
        es[t] = e;
        lmax = fmaxf(lmax, e);
    }
    rbuf[threadIdx.x] = lmax;
    __syncthreads();
    for (int s = 128; s > 0; s >>= 1) {
        if (threadIdx.x < s)
            rbuf[threadIdx.x] = fmaxf(rbuf[threadIdx.x], rbuf[threadIdx.x + s]);
        __syncthreads();
    }
    float mx = rbuf[0];
    __syncthreads();

    float lsum = 0.0f;
    for (int t = threadIdx.x; t < TLEN; t += 256) {
        float v = expf(es[t] - mx);
        es[t] = v;
        lsum += v;
    }
    rbuf[threadIdx.x] = lsum;
    __syncthreads();
    for (int s = 128; s > 0; s >>= 1) {
        if (threadIdx.x < s)
            rbuf[threadIdx.x] += rbuf[threadIdx.x + s];
        __syncthreads();
    }
    float inv = 1.0f / rbuf[0];
    for (int t = threadIdx.x; t < TLEN; t += 256)
        out_w[b * TLEN + t] = es[t] * inv;
}

// ---------------- kernel F: partial weighted sums ------------------------------------
__global__ void wsum_kernel(const float* __restrict__ enc,
                            const float* __restrict__ w) {
    int b  = blockIdx.x;
    int tc = blockIdx.y;
    __shared__ float ws[128];
    int t0 = tc * 128;
    if (threadIdx.x < 128)
        ws[threadIdx.x] = w[b * TLEN + t0 + threadIdx.x];
    __syncthreads();

    int d = threadIdx.x;
    float a0 = 0, a1 = 0, a2 = 0, a3 = 0;
    const float* base = enc + ((size_t)b * TLEN + t0) * DIN;
    #pragma unroll 4
    for (int tt = 0; tt < 128; tt++) {
        const float* r = base + (size_t)tt * DIN;
        float wv = ws[tt];
        a0 += r[d]       * wv;
        a1 += r[d + 256] * wv;
        a2 += r[d + 512] * wv;
        a3 += r[d + 768] * wv;
    }
    float* cp = g_cpart + ((size_t)tc * BATCH + b) * DIN;
    cp[d]       = a0;
    cp[d + 256] = a1;
    cp[d + 512] = a2;
    cp[d + 768] = a3;
}

// ---------------- kernel G: reduce context partials ----------------------------------
__global__ void creduce_kernel(float* __restrict__ out_c) {
    int i = blockIdx.x * blockDim.x + threadIdx.x;
    if (i >= BATCH * DIN) return;
    float s = 0.0f;
    #pragma unroll
    for (int tc = 0; tc < TCHUNKS; tc++)
        s += g_cpart[(size_t)tc * BATCH * DIN + i];
    out_c[i] = s;
}

// ---------------- launch -------------------------------------------------------------
extern "C" void kernel_launch(void* const* d_in, const int* in_sizes, int n_in,
                              void* d_out, int out_size) {
    const float* enc      = (const float*)d_in[0];   // (32,2048,1024)
    const int*   lens     = (const int*)  d_in[1];   // (32,)
    const float* dec_z    = (const float*)d_in[2];   // (32,1024)
    const float* att_prev = (const float*)d_in[3];   // (32,2048)
    const float* W_enc    = (const float*)d_in[4];   // (1024,512)
    const float* b_enc    = (const float*)d_in[5];   // (512,)
    const float* W_dec    = (const float*)d_in[6];   // (1024,512)
    const float* W_att    = (const float*)d_in[7];   // (32,512)
    const float* conv_w   = (const float*)d_in[8];   // (32,1,31)
    const float* W_g      = (const float*)d_in[9];   // (512,1)
    const float* b_g      = (const float*)d_in[10];  // (1,)

    float* out   = (float*)d_out;
    float* out_c = out;                  // (32,1024)
    float* out_w = out + BATCH * DIN;    // (32,2048)

    cudaFuncSetAttribute(energy_mma, cudaFuncAttributeMaxDynamicSharedMemorySize, SMEM_TOTAL);

    bias_kernel<<<BATCH, NATT>>>(dec_z, W_dec, b_enc);
    conv_kernel<<<MROWS / 256, 256>>>(att_prev, conv_w);
    wprep_kernel<<<NATT, 256>>>(W_enc, W_att);
    energy_mma<<<dim3(NSLICES, MROWS / 128), 256, SMEM_TOTAL>>>(enc, W_g);
    softmax_kernel<<<BATCH, 256>>>(lens, b_g, out_w);
    wsum_kernel<<<dim3(BATCH, TCHUNKS), 256>>>(enc, out_w);
    creduce_kernel<<<(BATCH * DIN + 255) / 256, 256>>>(out_c);
}